// round 4
// baseline (speedup 1.0000x reference)
#include <cuda_runtime.h>

#define NUM_NODES 1000000
#define NUM_EDGES 16000000
#define F  6

// Split feature tables: lo = 4 floats (16B row), hi = 2 floats (8B row).
// 24 MB per logical table instead of 32 MB -> better L2 residency,
// and the hi atomic is red.v2 (8B) instead of red.v4 (16B).
__device__ __align__(128) float g_lox[NUM_NODES * 4];
__device__ __align__(128) float g_hix[NUM_NODES * 2];
__device__ __align__(128) float g_loa[NUM_NODES * 4];
__device__ __align__(128) float g_hia[NUM_NODES * 2];
__device__ __align__(128) float g_loh[NUM_NODES * 4];
__device__ __align__(128) float g_hih[NUM_NODES * 2];
__device__ int g_idx_is32;   // 1 if edge_index stored as int32

// ---------------------------------------------------------------------------
// Kernel 0: detect edge-index dtype. int64 indices < 1M have zero high words;
// int32 data read as int64 fuses two indices -> huge values. Runs every launch.
// ---------------------------------------------------------------------------
__global__ void detect_kernel(const long long* __restrict__ ei) {
    __shared__ int bad;
    if (threadIdx.x == 0) bad = 0;
    __syncthreads();
    #pragma unroll
    for (int r = 0; r < 16; r++) {
        long long v = ei[threadIdx.x + r * 256];
        if ((unsigned long long)v >= (unsigned long long)NUM_NODES) bad = 1;
    }
    __syncthreads();
    if (threadIdx.x == 0) g_idx_is32 = bad;
}

// ---------------------------------------------------------------------------
// Kernel 1: split x into lo/hi tables and zero the accumulators.
// 2 nodes per thread: 48B of x = 3 aligned float4 loads.
// ---------------------------------------------------------------------------
__global__ void prep_kernel(const float* __restrict__ x) {
    int i = blockIdx.x * blockDim.x + threadIdx.x;   // node-pair id
    if (i >= NUM_NODES / 2) return;
    const float4* px = reinterpret_cast<const float4*>(x + (size_t)i * 12);
    float4 a = px[0], b = px[1], c = px[2];

    float4* lo = reinterpret_cast<float4*>(g_lox) + (size_t)2 * i;
    float2* hi = reinterpret_cast<float2*>(g_hix) + (size_t)2 * i;
    lo[0] = make_float4(a.x, a.y, a.z, a.w);
    hi[0] = make_float2(b.x, b.y);
    lo[1] = make_float4(b.z, b.w, c.x, c.y);
    hi[1] = make_float2(c.z, c.w);

    float4 z = make_float4(0.f, 0.f, 0.f, 0.f);
    float4* la = reinterpret_cast<float4*>(g_loa) + (size_t)2 * i;
    la[0] = z; la[1] = z;
    reinterpret_cast<float4*>(g_hia)[i] = z;   // two 8B hi rows = one 16B store
}

__device__ __forceinline__ void red_add_v4(float* p, float4 v) {
    asm volatile("red.global.add.v4.f32 [%0], {%1, %2, %3, %4};"
                 :: "l"(p), "f"(v.x), "f"(v.y), "f"(v.z), "f"(v.w) : "memory");
}
__device__ __forceinline__ void red_add_v2(float* p, float2 v) {
    asm volatile("red.global.add.v2.f32 [%0], {%1, %2};"
                 :: "l"(p), "f"(v.x), "f"(v.y) : "memory");
}

// ---------------------------------------------------------------------------
// Kernel 2/4: edge scatter, 4 edges/thread.
// Index loads are streaming (__ldcs, evict-first) so the 128MB index stream
// does not evict the L2-resident feature tables. Gathers are front-batched
// for MLP, then all 8 reds issue.
// ---------------------------------------------------------------------------
template <int PHASE>
__global__ void scatter_kernel(const void* __restrict__ ei) {
    int i = blockIdx.x * blockDim.x + threadIdx.x;   // edge-quad id
    if (i >= NUM_EDGES / 4) return;
    const float4* lot = PHASE ? reinterpret_cast<const float4*>(g_loh)
                              : reinterpret_cast<const float4*>(g_lox);
    const float2* hit = PHASE ? reinterpret_cast<const float2*>(g_hih)
                              : reinterpret_cast<const float2*>(g_hix);

    unsigned s[4], d[4];
    if (g_idx_is32) {
        const int* base = (const int*)ei;
        int4 sv = __ldcs(reinterpret_cast<const int4*>(base) + i);
        int4 dv = __ldcs(reinterpret_cast<const int4*>(base + NUM_EDGES) + i);
        s[0] = sv.x; s[1] = sv.y; s[2] = sv.z; s[3] = sv.w;
        d[0] = dv.x; d[1] = dv.y; d[2] = dv.z; d[3] = dv.w;
    } else {
        const long long* base = (const long long*)ei;
        longlong2 s0 = __ldcs(reinterpret_cast<const longlong2*>(base) + 2 * i);
        longlong2 s1 = __ldcs(reinterpret_cast<const longlong2*>(base) + 2 * i + 1);
        longlong2 d0 = __ldcs(reinterpret_cast<const longlong2*>(base + NUM_EDGES) + 2 * i);
        longlong2 d1 = __ldcs(reinterpret_cast<const longlong2*>(base + NUM_EDGES) + 2 * i + 1);
        s[0] = (unsigned)s0.x; s[1] = (unsigned)s0.y; s[2] = (unsigned)s1.x; s[3] = (unsigned)s1.y;
        d[0] = (unsigned)d0.x; d[1] = (unsigned)d0.y; d[2] = (unsigned)d1.x; d[3] = (unsigned)d1.y;
    }

    bool ok[4];
    float4 lo[4];
    float2 hi[4];
    #pragma unroll
    for (int e = 0; e < 4; e++) {
        ok[e] = (s[e] < NUM_NODES) && (d[e] < NUM_NODES);
        if (ok[e]) {
            lo[e] = lot[s[e]];
            hi[e] = hit[s[e]];
        }
    }
    #pragma unroll
    for (int e = 0; e < 4; e++) {
        if (ok[e]) {
            red_add_v4(g_loa + (size_t)d[e] * 4, lo[e]);
            red_add_v2(g_hia + (size_t)d[e] * 2, hi[e]);
        }
    }
}

// ---------------------------------------------------------------------------
// Kernel 3: layer-1 transform. h = b + agg*Wrel^T + x*Wroot^T.
// Writes split h tables, re-zeros accumulators for layer 2.
// ---------------------------------------------------------------------------
__global__ void transform1_kernel(const float* __restrict__ Wrel,
                                  const float* __restrict__ Wroot,
                                  const float* __restrict__ b) {
    __shared__ float swr[36], swo[36], sb[6];
    int t = threadIdx.x;
    if (t < 36)        swr[t]      = Wrel[t];
    else if (t < 72)   swo[t - 36] = Wroot[t - 36];
    else if (t < 78)   sb[t - 72]  = b[t - 72];
    __syncthreads();

    int i = blockIdx.x * blockDim.x + t;
    if (i >= NUM_NODES) return;

    float4 a0 = reinterpret_cast<const float4*>(g_loa)[i];
    float2 a1 = reinterpret_cast<const float2*>(g_hia)[i];
    float4 x0 = reinterpret_cast<const float4*>(g_lox)[i];
    float2 x1 = reinterpret_cast<const float2*>(g_hix)[i];

    float ag[6] = {a0.x, a0.y, a0.z, a0.w, a1.x, a1.y};
    float xv[6] = {x0.x, x0.y, x0.z, x0.w, x1.x, x1.y};

    float h[6];
    #pragma unroll
    for (int k = 0; k < 6; k++) {
        float acc = sb[k];
        #pragma unroll
        for (int j = 0; j < 6; j++) {
            acc = fmaf(ag[j], swr[k * 6 + j], acc);
            acc = fmaf(xv[j], swo[k * 6 + j], acc);
        }
        h[k] = acc;
    }

    reinterpret_cast<float4*>(g_loh)[i] = make_float4(h[0], h[1], h[2], h[3]);
    reinterpret_cast<float2*>(g_hih)[i] = make_float2(h[4], h[5]);
    // re-zero accumulators (scatter1 atomics are complete at this launch)
    reinterpret_cast<float4*>(g_loa)[i] = make_float4(0.f, 0.f, 0.f, 0.f);
    reinterpret_cast<float2*>(g_hia)[i] = make_float2(0.f, 0.f);
}

// ---------------------------------------------------------------------------
// Kernel 5: layer-2 transform + argmax + one-hot. 2 nodes/thread so the
// 6-float output rows pack into 3 aligned float4 stores (48B per pair).
// ---------------------------------------------------------------------------
__global__ void transform2_kernel(const float* __restrict__ Wrel,
                                  const float* __restrict__ Wroot,
                                  const float* __restrict__ b,
                                  float* __restrict__ out) {
    __shared__ float swr[36], swo[36], sb[6];
    int t = threadIdx.x;
    if (t < 36)        swr[t]      = Wrel[t];
    else if (t < 72)   swo[t - 36] = Wroot[t - 36];
    else if (t < 78)   sb[t - 72]  = b[t - 72];
    __syncthreads();

    int i = blockIdx.x * blockDim.x + t;   // node-pair id
    if (i >= NUM_NODES / 2) return;

    float o[12];
    #pragma unroll
    for (int n = 0; n < 2; n++) {
        int node = 2 * i + n;
        float4 a0 = reinterpret_cast<const float4*>(g_loa)[node];
        float2 a1 = reinterpret_cast<const float2*>(g_hia)[node];
        float4 x0 = reinterpret_cast<const float4*>(g_loh)[node];
        float2 x1 = reinterpret_cast<const float2*>(g_hih)[node];

        float ag[6] = {a0.x, a0.y, a0.z, a0.w, a1.x, a1.y};
        float xv[6] = {x0.x, x0.y, x0.z, x0.w, x1.x, x1.y};

        float h[6];
        #pragma unroll
        for (int k = 0; k < 6; k++) {
            float acc = sb[k];
            #pragma unroll
            for (int j = 0; j < 6; j++) {
                acc = fmaf(ag[j], swr[k * 6 + j], acc);
                acc = fmaf(xv[j], swo[k * 6 + j], acc);
            }
            h[k] = acc;
        }
        int best = 0; float bv = h[0];
        #pragma unroll
        for (int k = 1; k < 6; k++)
            if (h[k] > bv) { bv = h[k]; best = k; }   // first-max wins = jnp.argmax
        #pragma unroll
        for (int k = 0; k < 6; k++)
            o[n * 6 + k] = (k == best) ? 1.f : 0.f;
    }
    float4* po = reinterpret_cast<float4*>(out + (size_t)i * 12);
    po[0] = make_float4(o[0], o[1], o[2],  o[3]);
    po[1] = make_float4(o[4], o[5], o[6],  o[7]);
    po[2] = make_float4(o[8], o[9], o[10], o[11]);
}

extern "C" void kernel_launch(void* const* d_in, const int* in_sizes, int n_in,
                              void* d_out, int out_size) {
    const float* x      = (const float*)d_in[0];
    const void*  ei     = d_in[1];               // int32 or int64: detected on device
    const float* Wrel1  = (const float*)d_in[2];
    const float* Wroot1 = (const float*)d_in[3];
    const float* b1     = (const float*)d_in[4];
    const float* Wrel2  = (const float*)d_in[5];
    const float* Wroot2 = (const float*)d_in[6];
    const float* b2     = (const float*)d_in[7];
    float*       out    = (float*)d_out;

    const int BLK = 256;
    const int pair_grid = (NUM_NODES / 2 + BLK - 1) / BLK;
    const int node_grid = (NUM_NODES + BLK - 1) / BLK;
    const int edge_grid = (NUM_EDGES / 4 + BLK - 1) / BLK;

    detect_kernel<<<1, 256>>>((const long long*)ei);
    // Layer 1
    prep_kernel<<<pair_grid, BLK>>>(x);
    scatter_kernel<0><<<edge_grid, BLK>>>(ei);
    transform1_kernel<<<node_grid, BLK>>>(Wrel1, Wroot1, b1);
    // Layer 2
    scatter_kernel<1><<<edge_grid, BLK>>>(ei);
    transform2_kernel<<<pair_grid, BLK>>>(Wrel2, Wroot2, b2, out);
}

// round 5
// speedup vs baseline: 1.1899x; 1.1899x over previous
#include <cuda_runtime.h>

#define NUM_NODES 1000000
#define NUM_EDGES 16000000
#define F  6
#define FP 8   // padded feature width: 32B row = one L2 sector, lo+hi share a line

// Scratch: device globals (no allocation allowed anywhere).
__device__ __align__(128) float g_x8 [NUM_NODES * FP];  // padded copy of x
__device__ __align__(128) float g_agg[NUM_NODES * FP];  // scatter-add accumulator
__device__ __align__(128) float g_h8 [NUM_NODES * FP];  // padded layer-1 output
__device__ int g_idx_is32;                              // 1 if edge_index is int32

// ---------------------------------------------------------------------------
// Kernel 0: detect edge-index dtype. int64 indices < 1M have zero high words;
// int32 data read as int64 fuses two indices -> huge values. Runs every launch.
// ---------------------------------------------------------------------------
__global__ void detect_kernel(const long long* __restrict__ ei) {
    __shared__ int bad;
    if (threadIdx.x == 0) bad = 0;
    __syncthreads();
    #pragma unroll
    for (int r = 0; r < 16; r++) {
        long long v = ei[threadIdx.x + r * 256];
        if ((unsigned long long)v >= (unsigned long long)NUM_NODES) bad = 1;
    }
    __syncthreads();
    if (threadIdx.x == 0) g_idx_is32 = bad;
}

// ---------------------------------------------------------------------------
// Kernel 1: pad x into g_x8 (zeros in lanes 6,7) and zero g_agg.
// ---------------------------------------------------------------------------
__global__ void prep_kernel(const float* __restrict__ x) {
    int i = blockIdx.x * blockDim.x + threadIdx.x;
    if (i >= NUM_NODES) return;
    const float* xr = x + (size_t)i * F;
    float4 lo = make_float4(xr[0], xr[1], xr[2], xr[3]);
    float4 hi = make_float4(xr[4], xr[5], 0.f, 0.f);
    float4* px = reinterpret_cast<float4*>(g_x8 + (size_t)i * FP);
    px[0] = lo; px[1] = hi;
    float4 z = make_float4(0.f, 0.f, 0.f, 0.f);
    float4* pa = reinterpret_cast<float4*>(g_agg + (size_t)i * FP);
    pa[0] = z; pa[1] = z;
}

__device__ __forceinline__ void red_add_v4(float* p, float4 v) {
    asm volatile("red.global.add.v4.f32 [%0], {%1, %2, %3, %4};"
                 :: "l"(p), "f"(v.x), "f"(v.y), "f"(v.z), "f"(v.w) : "memory");
}
__device__ __forceinline__ void red_add_v2(float* p, float2 v) {
    asm volatile("red.global.add.v2.f32 [%0], {%1, %2};"
                 :: "l"(p), "f"(v.x), "f"(v.y) : "memory");
}

__device__ __forceinline__ void do_edge(const float* __restrict__ feat,
                                        unsigned s, unsigned d) {
    if (s >= NUM_NODES || d >= NUM_NODES) return;   // no IMA possible
    const float* row = feat + (size_t)s * FP;
    float4 lo = *reinterpret_cast<const float4*>(row);      // same 32B sector...
    float2 hi = *reinterpret_cast<const float2*>(row + 4);  // ...as the lo load
    float* a = g_agg + (size_t)d * FP;
    red_add_v4(a,     lo);                                  // 16B atomic
    red_add_v2(a + 4, hi);                                  // 8B atomic (was 16B of zeros-add)
}

// ---------------------------------------------------------------------------
// Kernel 2/4: edge scatter. agg[dst] += feat[src]. 2 edges per thread.
// Index loads are streaming (__ldcs) so 128MB of index traffic doesn't evict
// the L2-resident feature/accumulator tables.
// ---------------------------------------------------------------------------
template <int PHASE>
__global__ void scatter_kernel(const void* __restrict__ ei) {
    int i = blockIdx.x * blockDim.x + threadIdx.x;
    if (i >= NUM_EDGES / 2) return;
    const float* feat = (PHASE == 0) ? g_x8 : g_h8;

    if (g_idx_is32) {
        const int* src = (const int*)ei;
        const int* dst = src + NUM_EDGES;
        int2 s2 = __ldcs(reinterpret_cast<const int2*>(src) + i);
        int2 d2 = __ldcs(reinterpret_cast<const int2*>(dst) + i);
        do_edge(feat, (unsigned)s2.x, (unsigned)d2.x);
        do_edge(feat, (unsigned)s2.y, (unsigned)d2.y);
    } else {
        const long long* src = (const long long*)ei;
        const long long* dst = src + NUM_EDGES;
        longlong2 s2 = __ldcs(reinterpret_cast<const longlong2*>(src) + i);
        longlong2 d2 = __ldcs(reinterpret_cast<const longlong2*>(dst) + i);
        do_edge(feat, (unsigned)s2.x, (unsigned)d2.x);
        do_edge(feat, (unsigned)s2.y, (unsigned)d2.y);
    }
}

// ---------------------------------------------------------------------------
// Kernel 3/5: per-node dense transform.
//   h[k] = b[k] + sum_j agg[j]*W_rel[k][j] + sum_j in[j]*W_root[k][j]
// FINAL=false : write padded h into g_h8, re-zero g_agg for layer 2.
// FINAL=true  : argmax (first-max wins, matches jnp.argmax) -> one-hot.
// ---------------------------------------------------------------------------
template <bool FINAL>
__global__ void transform_kernel(const float* __restrict__ Wrel,
                                 const float* __restrict__ Wroot,
                                 const float* __restrict__ b,
                                 float* __restrict__ out) {
    __shared__ float swr[36], swo[36], sb[6];
    int t = threadIdx.x;
    if (t < 36)        swr[t]      = Wrel[t];
    else if (t < 72)   swo[t - 36] = Wroot[t - 36];
    else if (t < 78)   sb[t - 72]  = b[t - 72];
    __syncthreads();

    int i = blockIdx.x * blockDim.x + t;
    if (i >= NUM_NODES) return;

    const float* in_feat = FINAL ? g_h8 : g_x8;

    const float4* pa = reinterpret_cast<const float4*>(g_agg + (size_t)i * FP);
    float4 a0 = pa[0], a1 = pa[1];
    const float4* px = reinterpret_cast<const float4*>(in_feat + (size_t)i * FP);
    float4 x0 = px[0], x1 = px[1];

    float ag[6] = {a0.x, a0.y, a0.z, a0.w, a1.x, a1.y};
    float xv[6] = {x0.x, x0.y, x0.z, x0.w, x1.x, x1.y};

    float h[6];
    #pragma unroll
    for (int k = 0; k < 6; k++) {
        float acc = sb[k];
        #pragma unroll
        for (int j = 0; j < 6; j++) {
            acc = fmaf(ag[j], swr[k * 6 + j], acc);
            acc = fmaf(xv[j], swo[k * 6 + j], acc);
        }
        h[k] = acc;
    }

    if (!FINAL) {
        float4 z = make_float4(0.f, 0.f, 0.f, 0.f);
        float4* paw = reinterpret_cast<float4*>(g_agg + (size_t)i * FP);
        paw[0] = z; paw[1] = z;
        float4* ph = reinterpret_cast<float4*>(g_h8 + (size_t)i * FP);
        ph[0] = make_float4(h[0], h[1], h[2], h[3]);
        ph[1] = make_float4(h[4], h[5], 0.f, 0.f);
    } else {
        int best = 0; float bv = h[0];
        #pragma unroll
        for (int k = 1; k < 6; k++)
            if (h[k] > bv) { bv = h[k]; best = k; }   // first-max wins = jnp.argmax
        float* po = out + (size_t)i * F;
        #pragma unroll
        for (int k = 0; k < 6; k++)
            po[k] = (k == best) ? 1.f : 0.f;
    }
}

extern "C" void kernel_launch(void* const* d_in, const int* in_sizes, int n_in,
                              void* d_out, int out_size) {
    const float* x      = (const float*)d_in[0];
    const void*  ei     = d_in[1];               // int32 or int64: detected on device
    const float* Wrel1  = (const float*)d_in[2];
    const float* Wroot1 = (const float*)d_in[3];
    const float* b1     = (const float*)d_in[4];
    const float* Wrel2  = (const float*)d_in[5];
    const float* Wroot2 = (const float*)d_in[6];
    const float* b2     = (const float*)d_in[7];
    float*       out    = (float*)d_out;

    const int BLK = 256;
    const int node_grid = (NUM_NODES + BLK - 1) / BLK;
    const int edge_grid = (NUM_EDGES / 2 + BLK - 1) / BLK;

    detect_kernel<<<1, 256>>>((const long long*)ei);
    // Layer 1
    prep_kernel<<<node_grid, BLK>>>(x);
    scatter_kernel<0><<<edge_grid, BLK>>>(ei);
    transform_kernel<false><<<node_grid, BLK>>>(Wrel1, Wroot1, b1, nullptr);
    // Layer 2
    scatter_kernel<1><<<edge_grid, BLK>>>(ei);
    transform_kernel<true><<<node_grid, BLK>>>(Wrel2, Wroot2, b2, out);
}